// round 12
// baseline (speedup 1.0000x reference)
#include <cuda_runtime.h>
#include <cuda_bf16.h>
#include <cstdint>

// ---------------- problem constants ----------------
#define TSEQ 2048
#define TD   64
#define TDK  128            // combined head dim [Q|Qpos]
#define BQ   64             // q rows per CTA (16 per warp)
#define BK   64             // kv rows per tile
#define NT   128            // 4 warps
#define NTILES (TSEQ/BK)    // 32

// ---------------- SMEM (bytes, dynamic), double buffered ----------------
// per buffer: KH [64][136]bf16 @0, KL @17408, VH [64][72]bf16 @34816, VL @44032
#define KPITCH 272
#define VPITCH 144
#define SM_KH 0
#define SM_KL 17408
#define SM_VH 34816
#define SM_VL 44032
#define BUFSZ 53248
#define SMEM_TOTAL (2*BUFSZ)          // 106,496 B -> 2 CTAs/SM = 212,992 B
// Q staging (prologue only, inside buffer 0): hi @0, lo @17408 (64 rows x 272 B)
#define SM_QH 0
#define SM_QL 17408

__device__ __forceinline__ uint32_t smem_u32(const void* p) {
    uint32_t a;
    asm("{ .reg .u64 t; cvta.to.shared.u64 t, %1; cvt.u32.u64 %0, t; }" : "=r"(a) : "l"(p));
    return a;
}
// pack two fp32 -> bf16x2 (e0 -> low half, e1 -> high half)
__device__ __forceinline__ uint32_t cvt2bf(float e1, float e0) {
    uint32_t r;
    asm("cvt.rn.bf16x2.f32 %0, %1, %2;" : "=r"(r) : "f"(e1), "f"(e0));
    return r;
}

#define HMMA(d, a, b0, b1)                                                       \
    asm volatile("mma.sync.aligned.m16n8k16.row.col.f32.bf16.bf16.f32 "          \
        "{%0,%1,%2,%3}, {%4,%5,%6,%7}, {%8,%9}, {%0,%1,%2,%3};"                  \
        : "+f"((d)[0]), "+f"((d)[1]), "+f"((d)[2]), "+f"((d)[3])                 \
        : "r"((a)[0]), "r"((a)[1]), "r"((a)[2]), "r"((a)[3]), "r"(b0), "r"(b1))

#define LDSM4(r0, r1, r2, r3, addr)                                              \
    asm volatile("ldmatrix.sync.aligned.m8n8.x4.shared.b16 {%0,%1,%2,%3}, [%4];" \
        : "=r"(r0), "=r"(r1), "=r"(r2), "=r"(r3) : "r"(addr))

#define LDSM4T(r0, r1, r2, r3, addr)                                             \
    asm volatile("ldmatrix.sync.aligned.m8n8.x4.trans.shared.b16 {%0,%1,%2,%3}, [%4];" \
        : "=r"(r0), "=r"(r1), "=r"(r2), "=r"(r3) : "r"(addr))

// split one float4 into hi/lo bf16x2 pairs, 8B stores at byte offsets
__device__ __forceinline__ void split_store(char* sm, uint32_t off_h, uint32_t off_l,
                                            float4 v) {
    uint32_t h01 = cvt2bf(v.y, v.x);
    uint32_t h23 = cvt2bf(v.w, v.z);
    float r0 = v.x - __uint_as_float(h01 << 16);
    float r1 = v.y - __uint_as_float(h01 & 0xFFFF0000u);
    float r2 = v.z - __uint_as_float(h23 << 16);
    float r3 = v.w - __uint_as_float(h23 & 0xFFFF0000u);
    *(uint2*)(sm + off_h) = make_uint2(h01, h23);
    *(uint2*)(sm + off_l) = make_uint2(cvt2bf(r1, r0), cvt2bf(r3, r2));
}

__global__ __launch_bounds__(NT, 2)
void sdpa_mma_occ2_kernel(const float* __restrict__ Qg,
                          const float* __restrict__ Kg,
                          const float* __restrict__ Vg,
                          const float* __restrict__ Qpg,
                          const float* __restrict__ Kpg,
                          float* __restrict__ Og)
{
    extern __shared__ char smem[];
    const uint32_t sbase = smem_u32(smem);

    const int tid  = threadIdx.x;
    const int wid  = tid >> 5;
    const int lane = tid & 31;

    const int bh = blockIdx.y;
    const int q0 = blockIdx.x * BQ;
    const size_t bh_off = (size_t)bh * TSEQ * TD;
    const float* Qb  = Qg  + bh_off;
    const float* Qpb = Qpg + bh_off;
    const float* Kb  = Kg  + bh_off;
    const float* Kpb = Kpg + bh_off;
    const float* Vb  = Vg  + bh_off;

    // per-thread load coordinates (fixed across tiles)
    const int kr = tid >> 5;                 // K rows: kr + 4*it
    const int kc = (tid & 31) << 2;          // K col (d) group
    const int vr = tid >> 4;                 // V rows: vr + 8*it
    const int vc = (tid & 15) << 2;          // V col group

    // ================= stage Q' (scaled), split hi/lo =================
    const float scale = 0.125f;
    #pragma unroll
    for (int it = 0; it < 16; it++) {
        int idx4 = tid + it * NT;
        int r = idx4 >> 5;                   // 64 rows, 32 float4/row
        int c = (idx4 & 31) << 2;
        const float* src = (c < TD) ? (Qb + (size_t)(q0 + r) * TD + c)
                                    : (Qpb + (size_t)(q0 + r) * TD + (c - TD));
        float4 v = *(const float4*)src;
        v.x *= scale; v.y *= scale; v.z *= scale; v.w *= scale;
        uint32_t o = (uint32_t)r * KPITCH + (uint32_t)c * 2;
        split_store(smem, SM_QH + o, SM_QL + o, v);
    }
    __syncthreads();

    // ----- extract Q a-fragments (warp rows 16w .. 16w+15) -----
    uint32_t qh[8][4], ql[8][4];
    {
        uint32_t row = (uint32_t)(16 * wid) + (lane & 7) + ((lane >> 3) & 1) * 8;
        uint32_t base_r = row * KPITCH;
        uint32_t cshift = ((uint32_t)(lane >> 4)) * 16;
        #pragma unroll
        for (int kk = 0; kk < 8; kk++) {
            uint32_t off = base_r + (uint32_t)kk * 32 + cshift;
            LDSM4(qh[kk][0], qh[kk][1], qh[kk][2], qh[kk][3], sbase + SM_QH + off);
            LDSM4(ql[kk][0], ql[kk][1], ql[kk][2], ql[kk][3], sbase + SM_QL + off);
        }
    }
    __syncthreads();   // Q staging region (buffer 0) free for K/V

    // ================= flash attention state =================
    float o_acc[8][4];
    #pragma unroll
    for (int i = 0; i < 8; i++)
        #pragma unroll
        for (int j = 0; j < 4; j++) o_acc[i][j] = 0.0f;
    float m0 = -1e30f, m1 = -1e30f, l0 = 0.0f, l1 = 0.0f;

    const uint32_t k_row  = (lane & 7) + ((lane >> 4) & 1) * 8;
    const uint32_t k_kseg = ((lane >> 3) & 1) * 16;
    const uint32_t v_row  = (lane & 7) + ((lane >> 3) & 1) * 8;
    const uint32_t v_col  = ((uint32_t)(lane >> 4)) * 16;

    for (int kt = 0; kt < NTILES; kt++) {
        const int k0 = kt * BK;
        const uint32_t bb = (kt & 1) ? (uint32_t)BUFSZ : 0u;

        // ---- load K'/V tile directly into buffer bb (other CTA hides latency) ----
        // safe: buffer bb last read by compute of tile kt-2, ordered by the
        // __syncthreads of tile kt-1.
        #pragma unroll
        for (int it = 0; it < 16; it++) {
            int r = kr + it * 4;
            const float* src = (kc < TD) ? (Kb + (size_t)(k0 + r) * TD + kc)
                                         : (Kpb + (size_t)(k0 + r) * TD + (kc - TD));
            float4 v = *(const float4*)src;
            uint32_t o = bb + (uint32_t)r * KPITCH + (uint32_t)kc * 2;
            split_store(smem, SM_KH + o, SM_KL + o, v);
        }
        #pragma unroll
        for (int it = 0; it < 8; it++) {
            int r = vr + it * 8;
            float4 v = *(const float4*)(Vb + (size_t)(k0 + r) * TD + vc);
            uint32_t o = bb + (uint32_t)r * VPITCH + (uint32_t)vc * 2;
            split_store(smem, SM_VH + o, SM_VL + o, v);
        }
        __syncthreads();

        // ---- S = Qh*Kh + Qh*Kl + Ql*Kh  (16x64 per warp) ----
        float s[8][4];
        #pragma unroll
        for (int i = 0; i < 8; i++)
            #pragma unroll
            for (int j = 0; j < 4; j++) s[i][j] = 0.0f;

        #pragma unroll
        for (int kk = 0; kk < 8; kk++) {
            #pragma unroll
            for (int np = 0; np < 4; np++) {
                uint32_t off = bb + (16u * np + k_row) * KPITCH + (uint32_t)kk * 32 + k_kseg;
                uint32_t h0, h1, h2, h3, e0, e1, e2, e3;
                LDSM4(h0, h1, h2, h3, sbase + SM_KH + off);
                LDSM4(e0, e1, e2, e3, sbase + SM_KL + off);
                HMMA(s[2 * np],     qh[kk], h0, h1);
                HMMA(s[2 * np],     ql[kk], h0, h1);
                HMMA(s[2 * np],     qh[kk], e0, e1);
                HMMA(s[2 * np + 1], qh[kk], h2, h3);
                HMMA(s[2 * np + 1], ql[kk], h2, h3);
                HMMA(s[2 * np + 1], qh[kk], e2, e3);
            }
        }

        // ---- online softmax (rows: lane/4 and lane/4+8) ----
        float tm0 = -1e30f, tm1 = -1e30f;
        #pragma unroll
        for (int i = 0; i < 8; i++) {
            tm0 = fmaxf(tm0, fmaxf(s[i][0], s[i][1]));
            tm1 = fmaxf(tm1, fmaxf(s[i][2], s[i][3]));
        }
        tm0 = fmaxf(tm0, __shfl_xor_sync(0xffffffffu, tm0, 1));
        tm0 = fmaxf(tm0, __shfl_xor_sync(0xffffffffu, tm0, 2));
        tm1 = fmaxf(tm1, __shfl_xor_sync(0xffffffffu, tm1, 1));
        tm1 = fmaxf(tm1, __shfl_xor_sync(0xffffffffu, tm1, 2));
        float mn0 = fmaxf(m0, tm0), mn1 = fmaxf(m1, tm1);
        float a0 = __expf(m0 - mn0), a1 = __expf(m1 - mn1);
        m0 = mn0; m1 = mn1;

        float rs0 = 0.0f, rs1 = 0.0f;
        uint32_t ph0[8], ph1[8], pl0[8], pl1[8];
        #pragma unroll
        for (int i = 0; i < 8; i++) {
            float p0 = __expf(s[i][0] - mn0);
            float p1 = __expf(s[i][1] - mn0);
            float p2 = __expf(s[i][2] - mn1);
            float p3 = __expf(s[i][3] - mn1);
            rs0 += p0 + p1; rs1 += p2 + p3;
            uint32_t h01 = cvt2bf(p1, p0);
            uint32_t h23 = cvt2bf(p3, p2);
            ph0[i] = h01; ph1[i] = h23;
            float r0 = p0 - __uint_as_float(h01 << 16);
            float r1 = p1 - __uint_as_float(h01 & 0xFFFF0000u);
            float r2 = p2 - __uint_as_float(h23 << 16);
            float r3 = p3 - __uint_as_float(h23 & 0xFFFF0000u);
            pl0[i] = cvt2bf(r1, r0);
            pl1[i] = cvt2bf(r3, r2);
        }
        rs0 += __shfl_xor_sync(0xffffffffu, rs0, 1);
        rs0 += __shfl_xor_sync(0xffffffffu, rs0, 2);
        rs1 += __shfl_xor_sync(0xffffffffu, rs1, 1);
        rs1 += __shfl_xor_sync(0xffffffffu, rs1, 2);
        l0 = l0 * a0 + rs0;
        l1 = l1 * a1 + rs1;

        #pragma unroll
        for (int i = 0; i < 8; i++) {
            o_acc[i][0] *= a0; o_acc[i][1] *= a0;
            o_acc[i][2] *= a1; o_acc[i][3] *= a1;
        }

        // ---- O += Ph*Vh + Ph*Vl + Pl*Vh ----
        #pragma unroll
        for (int kk = 0; kk < 4; kk++) {
            uint32_t aH[4] = { ph0[2 * kk], ph1[2 * kk], ph0[2 * kk + 1], ph1[2 * kk + 1] };
            uint32_t aL[4] = { pl0[2 * kk], pl1[2 * kk], pl0[2 * kk + 1], pl1[2 * kk + 1] };
            #pragma unroll
            for (int np = 0; np < 4; np++) {
                uint32_t off = bb + (16u * kk + v_row) * VPITCH + 32u * np + v_col;
                uint32_t h0, h1, h2, h3, e0, e1, e2, e3;
                LDSM4T(h0, h1, h2, h3, sbase + SM_VH + off);
                LDSM4T(e0, e1, e2, e3, sbase + SM_VL + off);
                HMMA(o_acc[2 * np],     aH, h0, h1);
                HMMA(o_acc[2 * np],     aL, h0, h1);
                HMMA(o_acc[2 * np],     aH, e0, e1);
                HMMA(o_acc[2 * np + 1], aH, h2, h3);
                HMMA(o_acc[2 * np + 1], aL, h2, h3);
                HMMA(o_acc[2 * np + 1], aH, e2, e3);
            }
        }
        // no trailing sync: next tile writes the OTHER buffer; reuse of this
        // buffer (tile kt+2) is ordered by tile kt+1's __syncthreads.
    }

    // ================= epilogue =================
    float inv0 = 1.0f / l0, inv1 = 1.0f / l1;
    int row0 = 16 * wid + (lane >> 2);
    int row1 = row0 + 8;
    int colb = 2 * (lane & 3);
    size_t obase = ((size_t)bh * TSEQ + q0);
    #pragma unroll
    for (int i = 0; i < 8; i++) {
        int col = 8 * i + colb;
        *(float2*)(Og + (obase + row0) * TD + col) =
            make_float2(o_acc[i][0] * inv0, o_acc[i][1] * inv0);
        *(float2*)(Og + (obase + row1) * TD + col) =
            make_float2(o_acc[i][2] * inv1, o_acc[i][3] * inv1);
    }
}

extern "C" void kernel_launch(void* const* d_in, const int* in_sizes, int n_in,
                              void* d_out, int out_size)
{
    const float* Q  = (const float*)d_in[0];
    const float* K  = (const float*)d_in[1];
    const float* V  = (const float*)d_in[2];
    const float* Qp = (const float*)d_in[3];
    const float* Kp = (const float*)d_in[4];
    float* O = (float*)d_out;

    cudaFuncSetAttribute(sdpa_mma_occ2_kernel,
                         cudaFuncAttributeMaxDynamicSharedMemorySize, SMEM_TOTAL);

    dim3 grid(TSEQ / BQ, 2 * 16);   // (32, 32) = 1024 CTAs
    sdpa_mma_occ2_kernel<<<grid, NT, SMEM_TOTAL>>>(Q, K, V, Qp, Kp, O);
}